// round 1
// baseline (speedup 1.0000x reference)
#include <cuda_runtime.h>

#define DEV_INLINE __device__ __forceinline__

constexpr int NN   = 1024;
constexpr int EE   = 65536;
constexpr int E2   = EE + NN;      // edges + self loops
constexpr int W1O  = 512;          // H*256
constexpr int C1   = 256;
constexpr int W2O  = 128;          // H*64
constexpr int C2   = 64;

// ---------------- scratch (device globals; no allocation allowed) -------------
__device__ float g_xp[2][NN * W1O];   // per-relation projected features (reused layer2, width 128)
__device__ float g_acc1[NN * W1O];    // layer1 accumulator -> h1 after epilogue
__device__ float g_acc2[NN * W2O];    // layer2 accumulator -> h2
__device__ float g_als[2][NN * 2];
__device__ float g_ald[2][NN * 2];
__device__ int   g_cnt[2][NN];
__device__ int   g_off[2][NN + 1];
__device__ int   g_cur[2][NN];
__device__ int   g_srcs[2][E2];
__device__ float g_s[NN];

// ---------------- block reduction helpers ----------------
template <int BLOCK>
DEV_INLINE float blockReduceMax(float v, float* red) {
    #pragma unroll
    for (int o = 16; o; o >>= 1) v = fmaxf(v, __shfl_xor_sync(0xffffffffu, v, o));
    int t = threadIdx.x;
    if ((t & 31) == 0) red[t >> 5] = v;
    __syncthreads();
    constexpr int NW = BLOCK / 32;
    if (t < 32) {
        float x = (t < NW) ? red[t] : -1e30f;
        #pragma unroll
        for (int o = 16; o; o >>= 1) x = fmaxf(x, __shfl_xor_sync(0xffffffffu, x, o));
        if (t == 0) red[0] = x;
    }
    __syncthreads();
    float r = red[0];
    __syncthreads();
    return r;
}

template <int BLOCK>
DEV_INLINE float blockReduceSum(float v, float* red) {
    #pragma unroll
    for (int o = 16; o; o >>= 1) v += __shfl_xor_sync(0xffffffffu, v, o);
    int t = threadIdx.x;
    if ((t & 31) == 0) red[t >> 5] = v;
    __syncthreads();
    constexpr int NW = BLOCK / 32;
    if (t < 32) {
        float x = (t < NW) ? red[t] : 0.f;
        #pragma unroll
        for (int o = 16; o; o >>= 1) x += __shfl_xor_sync(0xffffffffu, x, o);
        if (t == 0) red[0] = x;
    }
    __syncthreads();
    float r = red[0];
    __syncthreads();
    return r;
}

// ---------------- CSR build ----------------
__global__ void k_init_cnt() {
    int r = blockIdx.y;
    int n = blockIdx.x * blockDim.x + threadIdx.x;
    if (n < NN) g_cnt[r][n] = 1;   // self loop pre-counted
}

__global__ void k_count(const int* __restrict__ ei0, const int* __restrict__ ei1) {
    int e = blockIdx.x * blockDim.x + threadIdx.x;
    if (e < EE) {
        atomicAdd(&g_cnt[0][ei0[EE + e]], 1);
        atomicAdd(&g_cnt[1][ei1[EE + e]], 1);
    }
}

__global__ void k_scan() {   // one block per relation, 1024 threads
    int r = blockIdx.x;
    int t = threadIdx.x;
    __shared__ int sh[NN];
    int mine = g_cnt[r][t];
    sh[t] = mine;
    __syncthreads();
    #pragma unroll
    for (int d = 1; d < NN; d <<= 1) {
        int v = (t >= d) ? sh[t - d] : 0;
        __syncthreads();
        sh[t] += v;
        __syncthreads();
    }
    g_off[r][t + 1] = sh[t];
    if (t == 0) g_off[r][0] = 0;
    g_cur[r][t] = sh[t] - mine;   // exclusive prefix = fill cursor
}

__global__ void k_fill(const int* __restrict__ ei0, const int* __restrict__ ei1) {
    int e = blockIdx.x * blockDim.x + threadIdx.x;
    if (e < E2) {
        int s0, d0, s1, d1;
        if (e < EE) {
            s0 = ei0[e]; d0 = ei0[EE + e];
            s1 = ei1[e]; d1 = ei1[EE + e];
        } else {
            s0 = d0 = s1 = d1 = e - EE;
        }
        int p0 = atomicAdd(&g_cur[0][d0], 1); g_srcs[0][p0] = s0;
        int p1 = atomicAdd(&g_cur[1][d1], 1); g_srcs[1][p1] = s1;
    }
}

// ---------------- fp32 tiled GEMM: C[M,Nc] = A[M,K] @ B[K,Nc] ----------------
__global__ void k_gemm(const float* __restrict__ A, const float* __restrict__ B,
                       float* __restrict__ C, int M, int Nc, int K) {
    __shared__ float As[16][64];
    __shared__ float Bs[16][64];
    int bm = blockIdx.y * 64, bn = blockIdx.x * 64;
    int t = threadIdx.x;                 // 256 threads
    int tx = t & 15, ty = t >> 4;
    int am = t >> 2;                     // 0..63
    int ak = (t & 3) * 4;                // 0,4,8,12
    int bk = t >> 4;                     // 0..15
    int bn4 = (t & 15) * 4;              // 0..60

    float acc[4][4];
    #pragma unroll
    for (int i = 0; i < 4; i++)
        #pragma unroll
        for (int j = 0; j < 4; j++) acc[i][j] = 0.f;

    for (int k0 = 0; k0 < K; k0 += 16) {
        float4 av = *(const float4*)(A + (size_t)(bm + am) * K + k0 + ak);
        float4 bv = *(const float4*)(B + (size_t)(k0 + bk) * Nc + bn + bn4);
        As[ak + 0][am] = av.x;
        As[ak + 1][am] = av.y;
        As[ak + 2][am] = av.z;
        As[ak + 3][am] = av.w;
        *(float4*)&Bs[bk][bn4] = bv;
        __syncthreads();
        #pragma unroll
        for (int k = 0; k < 16; k++) {
            float ar[4], br[4];
            #pragma unroll
            for (int i = 0; i < 4; i++) ar[i] = As[k][ty * 4 + i];
            #pragma unroll
            for (int j = 0; j < 4; j++) br[j] = Bs[k][tx * 4 + j];
            #pragma unroll
            for (int i = 0; i < 4; i++)
                #pragma unroll
                for (int j = 0; j < 4; j++) acc[i][j] = fmaf(ar[i], br[j], acc[i][j]);
        }
        __syncthreads();
    }
    #pragma unroll
    for (int i = 0; i < 4; i++)
        #pragma unroll
        for (int j = 0; j < 4; j++)
            C[(size_t)(bm + ty * 4 + i) * Nc + bn + tx * 4 + j] = acc[i][j];
}

// ---------------- per-node attention logits ----------------
template <int C, int WOUT>
__global__ void k_attn(const float* __restrict__ xp, const float* __restrict__ asrc,
                       const float* __restrict__ adst, float* __restrict__ als,
                       float* __restrict__ ald) {
    int n = blockIdx.x;
    int t = threadIdx.x;   // 64 threads: warp h handles head h
    int h = t >> 5, lane = t & 31;
    const float* row = xp + (size_t)n * WOUT + h * C;
    float ss = 0.f, sd = 0.f;
    for (int c = lane; c < C; c += 32) {
        float v = row[c];
        ss = fmaf(v, asrc[h * C + c], ss);
        sd = fmaf(v, adst[h * C + c], sd);
    }
    #pragma unroll
    for (int o = 16; o; o >>= 1) {
        ss += __shfl_xor_sync(0xffffffffu, ss, o);
        sd += __shfl_xor_sync(0xffffffffu, sd, o);
    }
    if (lane == 0) {
        als[n * 2 + h] = ss;
        ald[n * 2 + h] = sd;
    }
}

// ---------------- dst-centric softmax + weighted gather ----------------
template <int WOUT, int C, int BLOCK>
__global__ void k_aggregate(const float* __restrict__ xp, const float* __restrict__ als,
                            const float* __restrict__ ald, const int* __restrict__ off,
                            const int* __restrict__ srcs, float* __restrict__ acc) {
    constexpr int CH = 512;
    constexpr int U = WOUT / BLOCK;
    __shared__ int   sh_src[CH];
    __shared__ float sh_e0[CH];
    __shared__ float sh_e1[CH];
    __shared__ float red[32];

    int dst = blockIdx.x, t = threadIdx.x;
    int o0 = off[dst], o1 = off[dst + 1];
    int range = o1 - o0;
    float ad0 = ald[dst * 2 + 0], ad1 = ald[dst * 2 + 1];

    // pass 1: per-head max of leaky-relu logits over incoming edges
    float mx0 = -1e30f, mx1 = -1e30f;
    for (int i = t; i < range; i += BLOCK) {
        int s = srcs[o0 + i];
        float l0 = als[s * 2 + 0] + ad0; l0 = l0 > 0.f ? l0 : 0.2f * l0;
        float l1 = als[s * 2 + 1] + ad1; l1 = l1 > 0.f ? l1 : 0.2f * l1;
        mx0 = fmaxf(mx0, l0);
        mx1 = fmaxf(mx1, l1);
    }
    mx0 = blockReduceMax<BLOCK>(mx0, red);
    mx1 = blockReduceMax<BLOCK>(mx1, red);

    int cols[U], heads[U];
    float a[U];
    #pragma unroll
    for (int u = 0; u < U; u++) {
        cols[u] = t + u * BLOCK;
        heads[u] = cols[u] / C;
        a[u] = 0.f;
    }

    float sum0 = 0.f, sum1 = 0.f;
    for (int base = 0; base < range; base += CH) {
        int nn = min(CH, range - base);
        __syncthreads();
        for (int i = t; i < nn; i += BLOCK) {
            int s = srcs[o0 + base + i];
            sh_src[i] = s;
            float l0 = als[s * 2 + 0] + ad0; l0 = l0 > 0.f ? l0 : 0.2f * l0;
            float l1 = als[s * 2 + 1] + ad1; l1 = l1 > 0.f ? l1 : 0.2f * l1;
            float e0 = expf(l0 - mx0);
            float e1 = expf(l1 - mx1);
            sh_e0[i] = e0; sh_e1[i] = e1;
            sum0 += e0; sum1 += e1;
        }
        __syncthreads();
        #pragma unroll 4
        for (int j = 0; j < nn; j++) {
            int s = sh_src[j];
            const float* row = xp + (size_t)s * WOUT;
            #pragma unroll
            for (int u = 0; u < U; u++) {
                float e = (heads[u] == 0) ? sh_e0[j] : sh_e1[j];
                a[u] = fmaf(e, row[cols[u]], a[u]);
            }
        }
    }
    sum0 = blockReduceSum<BLOCK>(sum0, red);
    sum1 = blockReduceSum<BLOCK>(sum1, red);
    float inv0 = 1.f / (sum0 + 1e-16f);
    float inv1 = 1.f / (sum1 + 1e-16f);
    #pragma unroll
    for (int u = 0; u < U; u++)
        acc[(size_t)dst * WOUT + cols[u]] += a[u] * (heads[u] == 0 ? inv0 : inv1);
}

// ---------------- misc ----------------
__global__ void k_zero(float* p, int n) {
    int i = blockIdx.x * blockDim.x + threadIdx.x;
    if (i < n) p[i] = 0.f;
}

__global__ void k_epi1(const float* __restrict__ b0, const float* __restrict__ b1) {
    int i = blockIdx.x * blockDim.x + threadIdx.x;   // NN*512 threads
    float v = g_acc1[i] + b0[i & 511] + b1[i & 511];
    g_acc1[i] = v > 0.f ? v : 0.f;
}

__global__ void k_epi2(const float* __restrict__ b0, const float* __restrict__ b1) {
    int i = blockIdx.x * blockDim.x + threadIdx.x;   // NN*128 threads
    g_acc2[i] += b0[i & 127] + b1[i & 127];
}

__global__ void k_score(const float* __restrict__ wlin) {
    int n = blockIdx.x, t = threadIdx.x;  // 128 threads
    __shared__ float red[4];
    float v = g_acc2[(size_t)n * W2O + t] * wlin[t];
    #pragma unroll
    for (int o = 16; o; o >>= 1) v += __shfl_xor_sync(0xffffffffu, v, o);
    if ((t & 31) == 0) red[t >> 5] = v;
    __syncthreads();
    if (t == 0) g_s[n] = red[0] + red[1] + red[2] + red[3];
}

__global__ void k_pair(float* __restrict__ out, const float* __restrict__ blin) {
    int idx = blockIdx.x * blockDim.x + threadIdx.x;   // NN*NN/4 threads
    float b = blin[0];
    int i = idx >> 8;             // row index (1024 floats = 256 float4 per row)
    int j4 = (idx & 255) << 2;
    float si = g_s[i] + b;
    float4 v;
    v.x = si + g_s[j4 + 0];
    v.y = si + g_s[j4 + 1];
    v.z = si + g_s[j4 + 2];
    v.w = si + g_s[j4 + 3];
    ((float4*)out)[idx] = v;
}

// ---------------- launch ----------------
extern "C" void kernel_launch(void* const* d_in, const int* in_sizes, int n_in,
                              void* d_out, int out_size) {
    const float* x    = (const float*)d_in[0];
    const int*   ei0  = (const int*)d_in[1];
    const int*   ei1  = (const int*)d_in[2];
    const float* W1[2]  = {(const float*)d_in[3],  (const float*)d_in[7]};
    const float* as1[2] = {(const float*)d_in[4],  (const float*)d_in[8]};
    const float* ad1[2] = {(const float*)d_in[5],  (const float*)d_in[9]};
    const float* b1[2]  = {(const float*)d_in[6],  (const float*)d_in[10]};
    const float* W2[2]  = {(const float*)d_in[11], (const float*)d_in[15]};
    const float* as2[2] = {(const float*)d_in[12], (const float*)d_in[16]};
    const float* ad2[2] = {(const float*)d_in[13], (const float*)d_in[17]};
    const float* b2[2]  = {(const float*)d_in[14], (const float*)d_in[18]};
    const float* wlin = (const float*)d_in[19];
    const float* blin = (const float*)d_in[20];
    float* out = (float*)d_out;

    float *xp, *acc1, *acc2, *als, *ald;
    int *offp, *srcsp;
    cudaGetSymbolAddress((void**)&xp,    g_xp);
    cudaGetSymbolAddress((void**)&acc1,  g_acc1);
    cudaGetSymbolAddress((void**)&acc2,  g_acc2);
    cudaGetSymbolAddress((void**)&als,   g_als);
    cudaGetSymbolAddress((void**)&ald,   g_ald);
    cudaGetSymbolAddress((void**)&offp,  g_off);
    cudaGetSymbolAddress((void**)&srcsp, g_srcs);

    float* xpr[2]  = {xp, xp + (size_t)NN * W1O};
    float* alsr[2] = {als, als + NN * 2};
    float* aldr[2] = {ald, ald + NN * 2};
    int*   offr[2]  = {offp, offp + (NN + 1)};
    int*   srcsr[2] = {srcsp, srcsp + E2};

    // CSR build (topology shared by both layers)
    k_init_cnt<<<dim3(NN / 256, 2), 256>>>();
    k_count<<<EE / 256, 256>>>(ei0, ei1);
    k_scan<<<2, 1024>>>();
    k_fill<<<(E2 + 255) / 256, 256>>>(ei0, ei1);

    // ---- layer 1: 256 -> 512 per relation ----
    for (int r = 0; r < 2; r++)
        k_gemm<<<dim3(W1O / 64, NN / 64), 256>>>(x, W1[r], xpr[r], NN, W1O, 256);
    for (int r = 0; r < 2; r++)
        k_attn<C1, W1O><<<NN, 64>>>(xpr[r], as1[r], ad1[r], alsr[r], aldr[r]);
    k_zero<<<NN * W1O / 256, 256>>>(acc1, NN * W1O);
    for (int r = 0; r < 2; r++)
        k_aggregate<W1O, C1, 256><<<NN, 256>>>(xpr[r], alsr[r], aldr[r], offr[r], srcsr[r], acc1);
    k_epi1<<<NN * W1O / 256, 256>>>(b1[0], b1[1]);

    // ---- layer 2: 512 -> 128 per relation ----
    for (int r = 0; r < 2; r++)
        k_gemm<<<dim3(W2O / 64, NN / 64), 256>>>(acc1, W2[r], xpr[r], NN, W2O, 512);
    for (int r = 0; r < 2; r++)
        k_attn<C2, W2O><<<NN, 64>>>(xpr[r], as2[r], ad2[r], alsr[r], aldr[r]);
    k_zero<<<NN * W2O / 256, 256>>>(acc2, NN * W2O);
    for (int r = 0; r < 2; r++)
        k_aggregate<W2O, C2, 128><<<NN, 128>>>(xpr[r], alsr[r], aldr[r], offr[r], srcsr[r], acc2);
    k_epi2<<<NN * W2O / 256, 256>>>(b2[0], b2[1]);

    // ---- collapsed pairwise output: out[i*N+j] = s[i]+s[j]+b ----
    k_score<<<NN, 128>>>(wlin);
    k_pair<<<NN * NN / 4 / 256, 256>>>(out, blin);
}

// round 2
// speedup vs baseline: 1.5095x; 1.5095x over previous
#include <cuda_runtime.h>

#define DEV_INLINE __device__ __forceinline__

constexpr int NN   = 1024;
constexpr int EE   = 65536;
constexpr int E2   = EE + NN;      // edges + self loops
constexpr int W1O  = 512;          // H*256
constexpr int C1   = 256;
constexpr int W2O  = 128;          // H*64
constexpr int C2   = 64;

// ---------------- scratch (device globals; no allocation allowed) -------------
__device__ float g_xp[2][NN * W1O];   // per-relation projected features (layer2 reuses width 128)
__device__ float g_h1[NN * W1O];      // layer1 output (relu'd)
__device__ float g_als[2][NN * 2];
__device__ float g_ald[2][NN * 2];
__device__ int   g_cnt[2][NN];
__device__ int   g_off[2][NN + 1];
__device__ int   g_cur[2][NN];
__device__ int   g_srcs[2][E2];
__device__ float g_s[NN];

// ---------------- block reduction helpers ----------------
template <int BLOCK>
DEV_INLINE float blockReduceMax(float v, float* red) {
    #pragma unroll
    for (int o = 16; o; o >>= 1) v = fmaxf(v, __shfl_xor_sync(0xffffffffu, v, o));
    int t = threadIdx.x;
    if ((t & 31) == 0) red[t >> 5] = v;
    __syncthreads();
    constexpr int NW = BLOCK / 32;
    if (t < 32) {
        float x = (t < NW) ? red[t] : -1e30f;
        #pragma unroll
        for (int o = 16; o; o >>= 1) x = fmaxf(x, __shfl_xor_sync(0xffffffffu, x, o));
        if (t == 0) red[0] = x;
    }
    __syncthreads();
    float r = red[0];
    __syncthreads();
    return r;
}

template <int BLOCK>
DEV_INLINE float blockReduceSum(float v, float* red) {
    #pragma unroll
    for (int o = 16; o; o >>= 1) v += __shfl_xor_sync(0xffffffffu, v, o);
    int t = threadIdx.x;
    if ((t & 31) == 0) red[t >> 5] = v;
    __syncthreads();
    constexpr int NW = BLOCK / 32;
    if (t < 32) {
        float x = (t < NW) ? red[t] : 0.f;
        #pragma unroll
        for (int o = 16; o; o >>= 1) x += __shfl_xor_sync(0xffffffffu, x, o);
        if (t == 0) red[0] = x;
    }
    __syncthreads();
    float r = red[0];
    __syncthreads();
    return r;
}

// ---------------- CSR build ----------------
__global__ void k_count(const int* __restrict__ ei0, const int* __restrict__ ei1) {
    int e = blockIdx.x * blockDim.x + threadIdx.x;
    if (e < EE) {
        atomicAdd(&g_cnt[0][ei0[EE + e]], 1);
        atomicAdd(&g_cnt[1][ei1[EE + e]], 1);
    }
}

__global__ void k_scan() {   // one block per relation, 1024 threads
    int r = blockIdx.x;
    int t = threadIdx.x;
    __shared__ int sh[NN];
    int mine = g_cnt[r][t] + 1;    // +1: self loop
    sh[t] = mine;
    __syncthreads();
    #pragma unroll
    for (int d = 1; d < NN; d <<= 1) {
        int v = (t >= d) ? sh[t - d] : 0;
        __syncthreads();
        sh[t] += v;
        __syncthreads();
    }
    g_off[r][t + 1] = sh[t];
    if (t == 0) g_off[r][0] = 0;
    g_cur[r][t] = sh[t] - mine;   // exclusive prefix = fill cursor
}

__global__ void k_fill(const int* __restrict__ ei0, const int* __restrict__ ei1) {
    int e = blockIdx.x * blockDim.x + threadIdx.x;
    if (e < E2) {
        int s0, d0, s1, d1;
        if (e < EE) {
            s0 = ei0[e]; d0 = ei0[EE + e];
            s1 = ei1[e]; d1 = ei1[EE + e];
        } else {
            s0 = d0 = s1 = d1 = e - EE;
        }
        int p0 = atomicAdd(&g_cur[0][d0], 1); g_srcs[0][p0] = s0;
        int p1 = atomicAdd(&g_cur[1][d1], 1); g_srcs[1][p1] = s1;
    }
}

// ---------------- fp32 tiled GEMM, both relations in one grid (z = relation) ----
// C_r[M,Nc] = A[M,K] @ B_r[K,Nc]
template <int TM, int TN, int TT>
__global__ void k_gemm(const float* __restrict__ A,
                       const float* __restrict__ B0, const float* __restrict__ B1,
                       float* __restrict__ C0, float* __restrict__ C1,
                       int Nc, int K) {
    const float* B = blockIdx.z ? B1 : B0;
    float*       C = blockIdx.z ? C1 : C0;

    __shared__ float As[16][TM];
    __shared__ float Bs[16][TN];

    constexpr int TXN = TN / 4;            // threads along N
    constexpr int PA  = TM / (TT / 4);     // A-load passes
    constexpr int RB  = TT / TXN;          // B rows per pass
    constexpr int PB  = 16 / RB;           // B-load passes

    int bm = blockIdx.y * TM, bn = blockIdx.x * TN;
    int t  = threadIdx.x;
    int tx = t % TXN, ty = t / TXN;
    int ak = (t & 3) * 4;

    float acc[4][4];
    #pragma unroll
    for (int i = 0; i < 4; i++)
        #pragma unroll
        for (int j = 0; j < 4; j++) acc[i][j] = 0.f;

    for (int k0 = 0; k0 < K; k0 += 16) {
        #pragma unroll
        for (int p = 0; p < PA; p++) {
            int am = p * (TT / 4) + (t >> 2);
            float4 av = *(const float4*)(A + (size_t)(bm + am) * K + k0 + ak);
            As[ak + 0][am] = av.x;
            As[ak + 1][am] = av.y;
            As[ak + 2][am] = av.z;
            As[ak + 3][am] = av.w;
        }
        #pragma unroll
        for (int p = 0; p < PB; p++) {
            int bk  = p * RB + t / TXN;
            int bn4 = (t % TXN) * 4;
            *(float4*)&Bs[bk][bn4] =
                *(const float4*)(B + (size_t)(k0 + bk) * Nc + bn + bn4);
        }
        __syncthreads();
        #pragma unroll
        for (int k = 0; k < 16; k++) {
            float ar[4], br[4];
            #pragma unroll
            for (int i = 0; i < 4; i++) ar[i] = As[k][ty * 4 + i];
            #pragma unroll
            for (int j = 0; j < 4; j++) br[j] = Bs[k][tx * 4 + j];
            #pragma unroll
            for (int i = 0; i < 4; i++)
                #pragma unroll
                for (int j = 0; j < 4; j++) acc[i][j] = fmaf(ar[i], br[j], acc[i][j]);
        }
        __syncthreads();
    }
    #pragma unroll
    for (int i = 0; i < 4; i++)
        #pragma unroll
        for (int j = 0; j < 4; j++)
            C[(size_t)(bm + ty * 4 + i) * Nc + bn + tx * 4 + j] = acc[i][j];
}

// ---------------- per-node attention logits (both relations, grid.y = rel) ----
template <int C, int WOUT>
__global__ void k_attn(const float* __restrict__ xp0, const float* __restrict__ xp1,
                       const float* __restrict__ as0, const float* __restrict__ as1,
                       const float* __restrict__ ad0, const float* __restrict__ ad1,
                       float* __restrict__ als, float* __restrict__ ald) {
    int r = blockIdx.y;
    const float* xp   = r ? xp1 : xp0;
    const float* asrc = r ? as1 : as0;
    const float* adst = r ? ad1 : ad0;
    float* alsr = als + (size_t)r * NN * 2;
    float* aldr = ald + (size_t)r * NN * 2;

    int n = blockIdx.x;
    int t = threadIdx.x;   // 64 threads: warp h handles head h
    int h = t >> 5, lane = t & 31;
    const float* row = xp + (size_t)n * WOUT + h * C;
    float ss = 0.f, sd = 0.f;
    for (int c = lane; c < C; c += 32) {
        float v = row[c];
        ss = fmaf(v, asrc[h * C + c], ss);
        sd = fmaf(v, adst[h * C + c], sd);
    }
    #pragma unroll
    for (int o = 16; o; o >>= 1) {
        ss += __shfl_xor_sync(0xffffffffu, ss, o);
        sd += __shfl_xor_sync(0xffffffffu, sd, o);
    }
    if (lane == 0) {
        alsr[n * 2 + h] = ss;
        aldr[n * 2 + h] = sd;
    }
}

// ---------------- fused dst-centric softmax+gather, BOTH relations per block ---
// LAYER==1: out = relu(sum_r agg_r + b0 + b1), written to h1out.
// LAYER==2: v = sum_r agg_r + b0 + b1; s[dst] = sum_col v*wlin  (h2 never stored).
template <int WOUT, int C, int BLOCK, int LAYER>
__global__ void k_agg(const float* __restrict__ xpA, const float* __restrict__ xpB,
                      const float* __restrict__ als, const float* __restrict__ ald,
                      const int* __restrict__ off, const int* __restrict__ srcs,
                      const float* __restrict__ b0, const float* __restrict__ b1,
                      float* __restrict__ h1out, const float* __restrict__ wlin,
                      float* __restrict__ sout) {
    constexpr int CH = 512;
    constexpr int U  = WOUT / BLOCK;
    __shared__ int   sh_src[CH];
    __shared__ float sh_e0[CH];
    __shared__ float sh_e1[CH];
    __shared__ float red[32];

    int dst = blockIdx.x, t = threadIdx.x;

    int cols[U], heads[U];
    float tot[U];
    #pragma unroll
    for (int u = 0; u < U; u++) {
        cols[u] = t + u * BLOCK;
        heads[u] = cols[u] / C;
        tot[u] = 0.f;
    }

    #pragma unroll
    for (int r = 0; r < 2; r++) {
        const float* xp    = r ? xpB : xpA;
        const float* alsr  = als + (size_t)r * NN * 2;
        const float* aldr  = ald + (size_t)r * NN * 2;
        const int*   offr  = off + (size_t)r * (NN + 1);
        const int*   srcsr = srcs + (size_t)r * E2;

        int o0 = offr[dst], o1 = offr[dst + 1];
        int range = o1 - o0;
        float ad0 = aldr[dst * 2 + 0], ad1 = aldr[dst * 2 + 1];

        // pass 1: per-head max of leaky-relu logits
        float mx0 = -1e30f, mx1 = -1e30f;
        for (int i = t; i < range; i += BLOCK) {
            int s = srcsr[o0 + i];
            float l0 = alsr[s * 2 + 0] + ad0; l0 = l0 > 0.f ? l0 : 0.2f * l0;
            float l1 = alsr[s * 2 + 1] + ad1; l1 = l1 > 0.f ? l1 : 0.2f * l1;
            mx0 = fmaxf(mx0, l0);
            mx1 = fmaxf(mx1, l1);
        }
        mx0 = blockReduceMax<BLOCK>(mx0, red);
        mx1 = blockReduceMax<BLOCK>(mx1, red);

        float a[U];
        #pragma unroll
        for (int u = 0; u < U; u++) a[u] = 0.f;
        float sum0 = 0.f, sum1 = 0.f;

        for (int base = 0; base < range; base += CH) {
            int nn = min(CH, range - base);
            __syncthreads();
            for (int i = t; i < nn; i += BLOCK) {
                int s = srcsr[o0 + base + i];
                sh_src[i] = s;
                float l0 = alsr[s * 2 + 0] + ad0; l0 = l0 > 0.f ? l0 : 0.2f * l0;
                float l1 = alsr[s * 2 + 1] + ad1; l1 = l1 > 0.f ? l1 : 0.2f * l1;
                float e0 = expf(l0 - mx0);
                float e1 = expf(l1 - mx1);
                sh_e0[i] = e0; sh_e1[i] = e1;
                sum0 += e0; sum1 += e1;
            }
            __syncthreads();
            #pragma unroll 4
            for (int j = 0; j < nn; j++) {
                int s = sh_src[j];
                const float* row = xp + (size_t)s * WOUT;
                #pragma unroll
                for (int u = 0; u < U; u++) {
                    float e = (heads[u] == 0) ? sh_e0[j] : sh_e1[j];
                    a[u] = fmaf(e, row[cols[u]], a[u]);
                }
            }
        }
        sum0 = blockReduceSum<BLOCK>(sum0, red);
        sum1 = blockReduceSum<BLOCK>(sum1, red);
        float inv0 = 1.f / (sum0 + 1e-16f);
        float inv1 = 1.f / (sum1 + 1e-16f);
        #pragma unroll
        for (int u = 0; u < U; u++)
            tot[u] = fmaf(a[u], (heads[u] == 0 ? inv0 : inv1), tot[u]);
    }

    if (LAYER == 1) {
        #pragma unroll
        for (int u = 0; u < U; u++) {
            float v = tot[u] + b0[cols[u]] + b1[cols[u]];
            h1out[(size_t)dst * WOUT + cols[u]] = v > 0.f ? v : 0.f;
        }
    } else {
        float v = tot[0] + b0[t] + b1[t];
        float p = v * wlin[t];
        p = blockReduceSum<BLOCK>(p, red);
        if (t == 0) sout[dst] = p;
    }
}

// ---------------- pairwise output: out[i*N+j] = s[i]+s[j]+b ----------------
__global__ void k_pair(float* __restrict__ out, const float* __restrict__ blin) {
    int idx = blockIdx.x * blockDim.x + threadIdx.x;   // NN*NN/4 threads
    float b = blin[0];
    int i = idx >> 8;             // 256 float4 per row
    int j4 = (idx & 255) << 2;
    float si = g_s[i] + b;
    float4 v;
    v.x = si + g_s[j4 + 0];
    v.y = si + g_s[j4 + 1];
    v.z = si + g_s[j4 + 2];
    v.w = si + g_s[j4 + 3];
    ((float4*)out)[idx] = v;
}

// ---------------- launch ----------------
extern "C" void kernel_launch(void* const* d_in, const int* in_sizes, int n_in,
                              void* d_out, int out_size) {
    const float* x    = (const float*)d_in[0];
    const int*   ei0  = (const int*)d_in[1];
    const int*   ei1  = (const int*)d_in[2];
    const float* W1[2]  = {(const float*)d_in[3],  (const float*)d_in[7]};
    const float* as1[2] = {(const float*)d_in[4],  (const float*)d_in[8]};
    const float* ad1[2] = {(const float*)d_in[5],  (const float*)d_in[9]};
    const float* b1[2]  = {(const float*)d_in[6],  (const float*)d_in[10]};
    const float* W2[2]  = {(const float*)d_in[11], (const float*)d_in[15]};
    const float* as2[2] = {(const float*)d_in[12], (const float*)d_in[16]};
    const float* ad2[2] = {(const float*)d_in[13], (const float*)d_in[17]};
    const float* b2[2]  = {(const float*)d_in[14], (const float*)d_in[18]};
    const float* wlin = (const float*)d_in[19];
    const float* blin = (const float*)d_in[20];
    float* out = (float*)d_out;

    float *xp, *h1, *als, *ald, *sp;
    int *cntp, *offp, *srcsp;
    cudaGetSymbolAddress((void**)&xp,    g_xp);
    cudaGetSymbolAddress((void**)&h1,    g_h1);
    cudaGetSymbolAddress((void**)&als,   g_als);
    cudaGetSymbolAddress((void**)&ald,   g_ald);
    cudaGetSymbolAddress((void**)&cntp,  g_cnt);
    cudaGetSymbolAddress((void**)&offp,  g_off);
    cudaGetSymbolAddress((void**)&srcsp, g_srcs);
    cudaGetSymbolAddress((void**)&sp,    g_s);

    float* xp0 = xp;
    float* xp1 = xp + (size_t)NN * W1O;

    // CSR build (topology shared by both layers)
    cudaMemsetAsync(cntp, 0, 2 * NN * sizeof(int));
    k_count<<<EE / 256, 256>>>(ei0, ei1);
    k_scan<<<2, 1024>>>();
    k_fill<<<(E2 + 255) / 256, 256>>>(ei0, ei1);

    // ---- layer 1: 256 -> 512 per relation (one launch, z = relation) ----
    k_gemm<64, 64, 256><<<dim3(W1O / 64, NN / 64, 2), 256>>>(
        x, W1[0], W1[1], xp0, xp1, W1O, 256);
    k_attn<C1, W1O><<<dim3(NN, 2), 64>>>(
        xp0, xp1, as1[0], as1[1], ad1[0], ad1[1], als, ald);
    k_agg<W1O, C1, 256, 1><<<NN, 256>>>(
        xp0, xp1, als, ald, offp, srcsp, b1[0], b1[1], h1, nullptr, nullptr);

    // ---- layer 2: 512 -> 128 per relation ----
    k_gemm<64, 32, 128><<<dim3(W2O / 32, NN / 64, 2), 128>>>(
        h1, W2[0], W2[1], xp0, xp1, W2O, 512);
    k_attn<C2, W2O><<<dim3(NN, 2), 64>>>(
        xp0, xp1, as2[0], as2[1], ad2[0], ad2[1], als, ald);
    k_agg<W2O, C2, 128, 2><<<NN, 128>>>(
        xp0, xp1, als, ald, offp, srcsp, b2[0], b2[1], nullptr, wlin, sp);

    // ---- collapsed pairwise output ----
    k_pair<<<NN * NN / 4 / 256, 256>>>(out, blin);
}

// round 3
// speedup vs baseline: 1.7723x; 1.1741x over previous
#include <cuda_runtime.h>

#define DEV_INLINE __device__ __forceinline__

constexpr int NN   = 1024;
constexpr int EE   = 65536;
constexpr int E2   = EE + NN;      // edges + self loops
constexpr int W1O  = 512;          // H*256
constexpr int C1   = 256;
constexpr int W2O  = 128;          // H*64
constexpr int C2   = 64;

// ---------------- scratch (device globals) -------------
__device__ float g_xp[2][NN * W1O];
__device__ float g_h1[NN * W1O];
__device__ float g_als[2][NN * 2];
__device__ float g_ald[2][NN * 2];
__device__ int   g_cnt[2][NN];
__device__ int   g_off[2][NN + 1];
__device__ int   g_cur[2][NN];
__device__ int   g_srcs[2][E2];
__device__ float g_s[NN];

// ---------------- block reduction helpers ----------------
template <int BLOCK>
DEV_INLINE float blockReduceMax(float v, float* red) {
    #pragma unroll
    for (int o = 16; o; o >>= 1) v = fmaxf(v, __shfl_xor_sync(0xffffffffu, v, o));
    int t = threadIdx.x;
    if ((t & 31) == 0) red[t >> 5] = v;
    __syncthreads();
    constexpr int NW = BLOCK / 32;
    if (t < 32) {
        float x = (t < NW) ? red[t] : -1e30f;
        #pragma unroll
        for (int o = 16; o; o >>= 1) x = fmaxf(x, __shfl_xor_sync(0xffffffffu, x, o));
        if (t == 0) red[0] = x;
    }
    __syncthreads();
    float r = red[0];
    __syncthreads();
    return r;
}

template <int BLOCK>
DEV_INLINE float blockReduceSum(float v, float* red) {
    #pragma unroll
    for (int o = 16; o; o >>= 1) v += __shfl_xor_sync(0xffffffffu, v, o);
    int t = threadIdx.x;
    if ((t & 31) == 0) red[t >> 5] = v;
    __syncthreads();
    constexpr int NW = BLOCK / 32;
    if (t < 32) {
        float x = (t < NW) ? red[t] : 0.f;
        #pragma unroll
        for (int o = 16; o; o >>= 1) x += __shfl_xor_sync(0xffffffffu, x, o);
        if (t == 0) red[0] = x;
    }
    __syncthreads();
    float r = red[0];
    __syncthreads();
    return r;
}

// =======================================================================
// FUSED launch 1: gemm1 (both relations) + edge counting
//   blocks [0,128): 128x64-tile fp32 GEMM, 8x4 micro-tile, reg prefetch
//   blocks [128,192): count 4 edges/thread/relation (MLP batched)
// =======================================================================
constexpr int G1_GEMM_BLOCKS  = (W1O / 64) * (NN / 128) * 2;   // 128
constexpr int G1_COUNT_BLOCKS = EE / 4 / 256;                  // 64

__global__ void __launch_bounds__(256)
k_gemm1_count(const float* __restrict__ A,
              const float* __restrict__ B0, const float* __restrict__ B1,
              float* __restrict__ C0, float* __restrict__ C1,
              const int* __restrict__ ei0, const int* __restrict__ ei1) {
    int bid = blockIdx.x;
    int t = threadIdx.x;

    if (bid >= G1_GEMM_BLOCKS) {
        // ---- count part ----
        int cid = bid - G1_GEMM_BLOCKS;
        int idx = cid * 256 + t;                 // int4 index into dst arrays
        int4 d0 = ((const int4*)(ei0 + EE))[idx];
        int4 d1 = ((const int4*)(ei1 + EE))[idx];
        atomicAdd(&g_cnt[0][d0.x], 1); atomicAdd(&g_cnt[0][d0.y], 1);
        atomicAdd(&g_cnt[0][d0.z], 1); atomicAdd(&g_cnt[0][d0.w], 1);
        atomicAdd(&g_cnt[1][d1.x], 1); atomicAdd(&g_cnt[1][d1.y], 1);
        atomicAdd(&g_cnt[1][d1.z], 1); atomicAdd(&g_cnt[1][d1.w], 1);
        return;
    }

    // ---- GEMM part: C_r = A[1024,256] @ B_r[256,512], tile 128x64 ----
    constexpr int K = 256, Nc = W1O;
    __shared__ float4 sh[768];                   // As 2048 floats + Bs 1024 floats
    float*  As  = (float*)sh;                    // [16][128]
    float4* As4 = sh;                            // row stride 32
    float4* Bs4 = sh + 512;                      // [16][16] float4

    int rel = bid >> 6;
    int r   = bid & 63;
    int bn  = (r & 7) * 64;
    int bm  = (r >> 3) * 128;
    const float* B = rel ? B1 : B0;
    float*       C = rel ? C1 : C0;

    int tx = t & 15, ty = t >> 4;
    int am = t >> 2, ak = (t & 3) * 4;

    float4 acc[8];
    #pragma unroll
    for (int i = 0; i < 8; i++) acc[i] = make_float4(0.f, 0.f, 0.f, 0.f);

    // prefetch k0 = 0
    float4 a_reg0 = *(const float4*)(A + (size_t)(bm + am) * K + ak);
    float4 a_reg1 = *(const float4*)(A + (size_t)(bm + am + 64) * K + ak);
    float4 b_reg  = *(const float4*)(B + (size_t)(t >> 4) * Nc + bn + (t & 15) * 4);

    for (int k0 = 0; k0 < K; k0 += 16) {
        As[(ak + 0) * 128 + am] = a_reg0.x;
        As[(ak + 1) * 128 + am] = a_reg0.y;
        As[(ak + 2) * 128 + am] = a_reg0.z;
        As[(ak + 3) * 128 + am] = a_reg0.w;
        As[(ak + 0) * 128 + am + 64] = a_reg1.x;
        As[(ak + 1) * 128 + am + 64] = a_reg1.y;
        As[(ak + 2) * 128 + am + 64] = a_reg1.z;
        As[(ak + 3) * 128 + am + 64] = a_reg1.w;
        Bs4[(t >> 4) * 16 + (t & 15)] = b_reg;
        __syncthreads();

        if (k0 + 16 < K) {
            a_reg0 = *(const float4*)(A + (size_t)(bm + am) * K + k0 + 16 + ak);
            a_reg1 = *(const float4*)(A + (size_t)(bm + am + 64) * K + k0 + 16 + ak);
            b_reg  = *(const float4*)(B + (size_t)(k0 + 16 + (t >> 4)) * Nc + bn + (t & 15) * 4);
        }

        #pragma unroll
        for (int k = 0; k < 16; k++) {
            float4 a0 = As4[k * 32 + ty * 2];
            float4 a1 = As4[k * 32 + ty * 2 + 1];
            float4 b  = Bs4[k * 16 + tx];
            float ar[8] = {a0.x, a0.y, a0.z, a0.w, a1.x, a1.y, a1.z, a1.w};
            #pragma unroll
            for (int i = 0; i < 8; i++) {
                acc[i].x = fmaf(ar[i], b.x, acc[i].x);
                acc[i].y = fmaf(ar[i], b.y, acc[i].y);
                acc[i].z = fmaf(ar[i], b.z, acc[i].z);
                acc[i].w = fmaf(ar[i], b.w, acc[i].w);
            }
        }
        __syncthreads();
    }
    #pragma unroll
    for (int i = 0; i < 8; i++)
        *(float4*)(C + (size_t)(bm + ty * 8 + i) * Nc + bn + tx * 4) = acc[i];
}

// =======================================================================
// scan (adds self loop)
// =======================================================================
__global__ void k_scan() {
    int r = blockIdx.x;
    int t = threadIdx.x;
    __shared__ int sh[NN];
    int mine = g_cnt[r][t] + 1;    // +1 self loop
    sh[t] = mine;
    __syncthreads();
    #pragma unroll
    for (int d = 1; d < NN; d <<= 1) {
        int v = (t >= d) ? sh[t - d] : 0;
        __syncthreads();
        sh[t] += v;
        __syncthreads();
    }
    g_off[r][t + 1] = sh[t];
    if (t == 0) g_off[r][0] = 0;
    g_cur[r][t] = sh[t] - mine;
}

// =======================================================================
// FUSED launch 2: CSR fill (4 edges/thread) + layer-1 attention logits
//   blocks [0,65): fill.  blocks [65,321): attn (warp per node-rel)
// =======================================================================
constexpr int F2_FILL_BLOCKS = E2 / 4 / 256;     // 65
constexpr int F2_ATTN_BLOCKS = NN * 2 / 8;       // 256

__global__ void __launch_bounds__(256)
k_fill_attn1(const int* __restrict__ ei0, const int* __restrict__ ei1,
             const float* __restrict__ xp0, const float* __restrict__ xp1,
             const float* __restrict__ as0, const float* __restrict__ as1,
             const float* __restrict__ ad0, const float* __restrict__ ad1,
             float* __restrict__ als, float* __restrict__ ald) {
    int bid = blockIdx.x;
    int t = threadIdx.x;

    if (bid < F2_FILL_BLOCKS) {
        int base = bid * 1024 + t * 4;
        if (base < EE) {   // blocks 0..63: pure edges, vectorized
            int idx = bid * 256 + t;
            int4 s0 = ((const int4*)ei0)[idx];
            int4 d0 = ((const int4*)(ei0 + EE))[idx];
            int4 s1 = ((const int4*)ei1)[idx];
            int4 d1 = ((const int4*)(ei1 + EE))[idx];
            int p;
            p = atomicAdd(&g_cur[0][d0.x], 1); g_srcs[0][p] = s0.x;
            p = atomicAdd(&g_cur[0][d0.y], 1); g_srcs[0][p] = s0.y;
            p = atomicAdd(&g_cur[0][d0.z], 1); g_srcs[0][p] = s0.z;
            p = atomicAdd(&g_cur[0][d0.w], 1); g_srcs[0][p] = s0.w;
            p = atomicAdd(&g_cur[1][d1.x], 1); g_srcs[1][p] = s1.x;
            p = atomicAdd(&g_cur[1][d1.y], 1); g_srcs[1][p] = s1.y;
            p = atomicAdd(&g_cur[1][d1.z], 1); g_srcs[1][p] = s1.z;
            p = atomicAdd(&g_cur[1][d1.w], 1); g_srcs[1][p] = s1.w;
        } else {           // block 64: self loops
            #pragma unroll
            for (int u = 0; u < 4; u++) {
                int n = base + u - EE;
                int p0 = atomicAdd(&g_cur[0][n], 1); g_srcs[0][p0] = n;
                int p1 = atomicAdd(&g_cur[1][n], 1); g_srcs[1][p1] = n;
            }
        }
        return;
    }

    // ---- attn1: warp per (node, rel); two heads of C=256 ----
    int idx  = (bid - F2_FILL_BLOCKS) * 8 + (t >> 5);
    int node = idx >> 1, rel = idx & 1;
    int lane = t & 31;
    const float4* row = (const float4*)((rel ? xp1 : xp0) + (size_t)node * W1O);
    const float4* av  = (const float4*)(rel ? as1 : as0);
    const float4* dv  = (const float4*)(rel ? ad1 : ad0);
    float ss0 = 0.f, sd0 = 0.f, ss1 = 0.f, sd1 = 0.f;
    #pragma unroll
    for (int i = 0; i < 4; i++) {
        float4 v = row[i * 32 + lane];
        float4 a = av[i * 32 + lane];
        float4 d = dv[i * 32 + lane];
        float ps = v.x * a.x + v.y * a.y + v.z * a.z + v.w * a.w;
        float pd = v.x * d.x + v.y * d.y + v.z * d.z + v.w * d.w;
        if (i < 2) { ss0 += ps; sd0 += pd; } else { ss1 += ps; sd1 += pd; }
    }
    #pragma unroll
    for (int o = 16; o; o >>= 1) {
        ss0 += __shfl_xor_sync(0xffffffffu, ss0, o);
        sd0 += __shfl_xor_sync(0xffffffffu, sd0, o);
        ss1 += __shfl_xor_sync(0xffffffffu, ss1, o);
        sd1 += __shfl_xor_sync(0xffffffffu, sd1, o);
    }
    if (lane == 0) {
        float* alsr = als + (size_t)rel * NN * 2;
        float* aldr = ald + (size_t)rel * NN * 2;
        alsr[node * 2 + 0] = ss0;
        alsr[node * 2 + 1] = ss1;
        aldr[node * 2 + 0] = sd0;
        aldr[node * 2 + 1] = sd1;
    }
}

// =======================================================================
// gemm2: C_r[1024,128] = h1[1024,512] @ W2_r, tile 64x32, 4x4 micro
// =======================================================================
__global__ void __launch_bounds__(128)
k_gemm2(const float* __restrict__ A,
        const float* __restrict__ B0, const float* __restrict__ B1,
        float* __restrict__ C0, float* __restrict__ C1) {
    constexpr int K = 512, Nc = W2O;
    __shared__ float4 sh[384];                   // As 1024 floats + Bs 512
    float*  As  = (float*)sh;
    float4* As4 = sh;                            // row stride 16
    float4* Bs4 = sh + 256;                      // [16][8]

    int bid = blockIdx.x;
    int rel = bid >> 6;
    int r   = bid & 63;
    int bn  = (r & 3) * 32;
    int bm  = (r >> 2) * 64;
    const float* B = rel ? B1 : B0;
    float*       C = rel ? C1 : C0;

    int t = threadIdx.x;
    int tx = t & 7, ty = t >> 3;
    int am = t >> 2, ak = (t & 3) * 4;

    float4 acc[4];
    #pragma unroll
    for (int i = 0; i < 4; i++) acc[i] = make_float4(0.f, 0.f, 0.f, 0.f);

    float4 a_reg0 = *(const float4*)(A + (size_t)(bm + am) * K + ak);
    float4 a_reg1 = *(const float4*)(A + (size_t)(bm + am + 32) * K + ak);
    float4 b_reg  = *(const float4*)(B + (size_t)(t >> 3) * Nc + bn + (t & 7) * 4);

    for (int k0 = 0; k0 < K; k0 += 16) {
        As[(ak + 0) * 64 + am] = a_reg0.x;
        As[(ak + 1) * 64 + am] = a_reg0.y;
        As[(ak + 2) * 64 + am] = a_reg0.z;
        As[(ak + 3) * 64 + am] = a_reg0.w;
        As[(ak + 0) * 64 + am + 32] = a_reg1.x;
        As[(ak + 1) * 64 + am + 32] = a_reg1.y;
        As[(ak + 2) * 64 + am + 32] = a_reg1.z;
        As[(ak + 3) * 64 + am + 32] = a_reg1.w;
        Bs4[(t >> 3) * 8 + (t & 7)] = b_reg;
        __syncthreads();

        if (k0 + 16 < K) {
            a_reg0 = *(const float4*)(A + (size_t)(bm + am) * K + k0 + 16 + ak);
            a_reg1 = *(const float4*)(A + (size_t)(bm + am + 32) * K + k0 + 16 + ak);
            b_reg  = *(const float4*)(B + (size_t)(k0 + 16 + (t >> 3)) * Nc + bn + (t & 7) * 4);
        }

        #pragma unroll
        for (int k = 0; k < 16; k++) {
            float4 a = As4[k * 16 + ty];
            float4 b = Bs4[k * 8 + tx];
            float ar[4] = {a.x, a.y, a.z, a.w};
            #pragma unroll
            for (int i = 0; i < 4; i++) {
                acc[i].x = fmaf(ar[i], b.x, acc[i].x);
                acc[i].y = fmaf(ar[i], b.y, acc[i].y);
                acc[i].z = fmaf(ar[i], b.z, acc[i].z);
                acc[i].w = fmaf(ar[i], b.w, acc[i].w);
            }
        }
        __syncthreads();
    }
    #pragma unroll
    for (int i = 0; i < 4; i++)
        *(float4*)(C + (size_t)(bm + ty * 4 + i) * Nc + bn + tx * 4) = acc[i];
}

// =======================================================================
// attn2: warp per (node, rel); two heads of C=64 (one float4 per lane)
// =======================================================================
__global__ void __launch_bounds__(256)
k_attn2(const float* __restrict__ xp0, const float* __restrict__ xp1,
        const float* __restrict__ as0, const float* __restrict__ as1,
        const float* __restrict__ ad0, const float* __restrict__ ad1,
        float* __restrict__ als, float* __restrict__ ald) {
    int t = threadIdx.x;
    int idx  = blockIdx.x * 8 + (t >> 5);
    int node = idx >> 1, rel = idx & 1;
    int lane = t & 31;
    const float4* row = (const float4*)((rel ? xp1 : xp0) + (size_t)node * W2O);
    const float4* av  = (const float4*)(rel ? as1 : as0);
    const float4* dv  = (const float4*)(rel ? ad1 : ad0);
    float4 v = row[lane];
    float4 a = av[lane];
    float4 d = dv[lane];
    float ss = v.x * a.x + v.y * a.y + v.z * a.z + v.w * a.w;
    float sd = v.x * d.x + v.y * d.y + v.z * d.z + v.w * d.w;
    #pragma unroll
    for (int o = 8; o; o >>= 1) {       // reduce within 16-lane head group
        ss += __shfl_xor_sync(0xffffffffu, ss, o);
        sd += __shfl_xor_sync(0xffffffffu, sd, o);
    }
    if ((lane & 15) == 0) {
        int h = lane >> 4;
        float* alsr = als + (size_t)rel * NN * 2;
        float* aldr = ald + (size_t)rel * NN * 2;
        alsr[node * 2 + h] = ss;
        aldr[node * 2 + h] = sd;
    }
}

// =======================================================================
// fused dst-centric softmax+gather (both relations)
// =======================================================================
template <int WOUT, int C, int BLOCK, int LAYER>
__global__ void k_agg(const float* __restrict__ xpA, const float* __restrict__ xpB,
                      const float* __restrict__ als, const float* __restrict__ ald,
                      const int* __restrict__ off, const int* __restrict__ srcs,
                      const float* __restrict__ b0, const float* __restrict__ b1,
                      float* __restrict__ h1out, const float* __restrict__ wlin,
                      float* __restrict__ sout) {
    constexpr int CH = 512;
    constexpr int U  = WOUT / BLOCK;
    __shared__ int   sh_src[CH];
    __shared__ float sh_e0[CH];
    __shared__ float sh_e1[CH];
    __shared__ float red[32];

    int dst = blockIdx.x, t = threadIdx.x;

    int cols[U], heads[U];
    float tot[U];
    #pragma unroll
    for (int u = 0; u < U; u++) {
        cols[u] = t + u * BLOCK;
        heads[u] = cols[u] / C;
        tot[u] = 0.f;
    }

    #pragma unroll
    for (int r = 0; r < 2; r++) {
        const float* xp    = r ? xpB : xpA;
        const float* alsr  = als + (size_t)r * NN * 2;
        const float* aldr  = ald + (size_t)r * NN * 2;
        const int*   offr  = off + (size_t)r * (NN + 1);
        const int*   srcsr = srcs + (size_t)r * E2;

        int o0 = offr[dst], o1 = offr[dst + 1];
        int range = o1 - o0;
        float ad0 = aldr[dst * 2 + 0], ad1 = aldr[dst * 2 + 1];

        float mx0 = -1e30f, mx1 = -1e30f;
        for (int i = t; i < range; i += BLOCK) {
            int s = srcsr[o0 + i];
            float l0 = alsr[s * 2 + 0] + ad0; l0 = l0 > 0.f ? l0 : 0.2f * l0;
            float l1 = alsr[s * 2 + 1] + ad1; l1 = l1 > 0.f ? l1 : 0.2f * l1;
            mx0 = fmaxf(mx0, l0);
            mx1 = fmaxf(mx1, l1);
        }
        mx0 = blockReduceMax<BLOCK>(mx0, red);
        mx1 = blockReduceMax<BLOCK>(mx1, red);

        float a[U];
        #pragma unroll
        for (int u = 0; u < U; u++) a[u] = 0.f;
        float sum0 = 0.f, sum1 = 0.f;

        for (int base = 0; base < range; base += CH) {
            int nn = min(CH, range - base);
            __syncthreads();
            for (int i = t; i < nn; i += BLOCK) {
                int s = srcsr[o0 + base + i];
                sh_src[i] = s;
                float l0 = alsr[s * 2 + 0] + ad0; l0 = l0 > 0.f ? l0 : 0.2f * l0;
                float l1 = alsr[s * 2 + 1] + ad1; l1 = l1 > 0.f ? l1 : 0.2f * l1;
                float e0 = expf(l0 - mx0);
                float e1 = expf(l1 - mx1);
                sh_e0[i] = e0; sh_e1[i] = e1;
                sum0 += e0; sum1 += e1;
            }
            __syncthreads();
            #pragma unroll 4
            for (int j = 0; j < nn; j++) {
                int s = sh_src[j];
                const float* row = xp + (size_t)s * WOUT;
                #pragma unroll
                for (int u = 0; u < U; u++) {
                    float e = (heads[u] == 0) ? sh_e0[j] : sh_e1[j];
                    a[u] = fmaf(e, row[cols[u]], a[u]);
                }
            }
        }
        sum0 = blockReduceSum<BLOCK>(sum0, red);
        sum1 = blockReduceSum<BLOCK>(sum1, red);
        float inv0 = 1.f / (sum0 + 1e-16f);
        float inv1 = 1.f / (sum1 + 1e-16f);
        #pragma unroll
        for (int u = 0; u < U; u++)
            tot[u] = fmaf(a[u], (heads[u] == 0 ? inv0 : inv1), tot[u]);
    }

    if (LAYER == 1) {
        #pragma unroll
        for (int u = 0; u < U; u++) {
            float v = tot[u] + b0[cols[u]] + b1[cols[u]];
            h1out[(size_t)dst * WOUT + cols[u]] = v > 0.f ? v : 0.f;
        }
    } else {
        float v = tot[0] + b0[t] + b1[t];
        float p = v * wlin[t];
        p = blockReduceSum<BLOCK>(p, red);
        if (t == 0) sout[dst] = p;
    }
}

// ---------------- pairwise output: out[i*N+j] = s[i]+s[j]+b ----------------
__global__ void k_pair(float* __restrict__ out, const float* __restrict__ blin) {
    int idx = blockIdx.x * blockDim.x + threadIdx.x;
    float b = blin[0];
    int i = idx >> 8;
    int j4 = (idx & 255) << 2;
    float si = g_s[i] + b;
    float4 v;
    v.x = si + g_s[j4 + 0];
    v.y = si + g_s[j4 + 1];
    v.z = si + g_s[j4 + 2];
    v.w = si + g_s[j4 + 3];
    ((float4*)out)[idx] = v;
}

// ---------------- launch ----------------
extern "C" void kernel_launch(void* const* d_in, const int* in_sizes, int n_in,
                              void* d_out, int out_size) {
    const float* x    = (const float*)d_in[0];
    const int*   ei0  = (const int*)d_in[1];
    const int*   ei1  = (const int*)d_in[2];
    const float* W1[2]  = {(const float*)d_in[3],  (const float*)d_in[7]};
    const float* as1[2] = {(const float*)d_in[4],  (const float*)d_in[8]};
    const float* ad1[2] = {(const float*)d_in[5],  (const float*)d_in[9]};
    const float* b1[2]  = {(const float*)d_in[6],  (const float*)d_in[10]};
    const float* W2[2]  = {(const float*)d_in[11], (const float*)d_in[15]};
    const float* as2[2] = {(const float*)d_in[12], (const float*)d_in[16]};
    const float* ad2[2] = {(const float*)d_in[13], (const float*)d_in[17]};
    const float* b2[2]  = {(const float*)d_in[14], (const float*)d_in[18]};
    const float* wlin = (const float*)d_in[19];
    const float* blin = (const float*)d_in[20];
    float* out = (float*)d_out;

    float *xp, *h1, *als, *ald, *sp;
    int *cntp, *offp, *srcsp;
    cudaGetSymbolAddress((void**)&xp,    g_xp);
    cudaGetSymbolAddress((void**)&h1,    g_h1);
    cudaGetSymbolAddress((void**)&als,   g_als);
    cudaGetSymbolAddress((void**)&ald,   g_ald);
    cudaGetSymbolAddress((void**)&cntp,  g_cnt);
    cudaGetSymbolAddress((void**)&offp,  g_off);
    cudaGetSymbolAddress((void**)&srcsp, g_srcs);
    cudaGetSymbolAddress((void**)&sp,    g_s);

    float* xp0 = xp;
    float* xp1 = xp + (size_t)NN * W1O;

    cudaMemsetAsync(cntp, 0, 2 * NN * sizeof(int));

    // launch 2: gemm1 (both rel) + edge count, overlapped
    k_gemm1_count<<<G1_GEMM_BLOCKS + G1_COUNT_BLOCKS, 256>>>(
        x, W1[0], W1[1], xp0, xp1, ei0, ei1);

    // launch 3: prefix scan
    k_scan<<<2, 1024>>>();

    // launch 4: CSR fill + attn1, overlapped
    k_fill_attn1<<<F2_FILL_BLOCKS + F2_ATTN_BLOCKS, 256>>>(
        ei0, ei1, xp0, xp1, as1[0], as1[1], ad1[0], ad1[1], als, ald);

    // launch 5: layer-1 aggregation (+bias+relu fused)
    k_agg<W1O, C1, 256, 1><<<NN, 256>>>(
        xp0, xp1, als, ald, offp, srcsp, b1[0], b1[1], h1, nullptr, nullptr);

    // launch 6: gemm2
    k_gemm2<<<128, 128>>>(h1, W2[0], W2[1], xp0, xp1);

    // launch 7: attn2
    k_attn2<<<NN * 2 / 8, 256>>>(
        xp0, xp1, as2[0], as2[1], ad2[0], ad2[1], als, ald);

    // launch 8: layer-2 aggregation (+bias+w_lin fused -> s)
    k_agg<W2O, C2, 128, 2><<<NN, 128>>>(
        xp0, xp1, als, ald, offp, srcsp, b2[0], b2[1], nullptr, wlin, sp);

    // launch 9: pairwise output
    k_pair<<<NN * NN / 4 / 256, 256>>>(out, blin);
}